// round 4
// baseline (speedup 1.0000x reference)
#include <cuda_runtime.h>

// ---------------------------------------------------------------------------
// RelativeDifferenceLoss: mean over N of (y==0 ? |x-y| : |x-y|/y)
// Single fused kernel: grid-wide partial sums + last-block-done final reduce.
// ---------------------------------------------------------------------------

#define NBLOCKS   2048          // 2048*256 = 2^19 threads; n4=2^23 -> 16 iters/thread
#define NTHREADS  256

__device__ float        g_partials[NBLOCKS];
__device__ unsigned int g_count = 0;   // reset by last block each launch

__device__ __forceinline__ float rel_term(float x, float y) {
    float ad = fabsf(x - y);
    return (y == 0.0f) ? ad : __fdividef(ad, y);   // signed y, matching reference
}

__device__ __forceinline__ float quad(float4 xv, float4 yv) {
    return rel_term(xv.x, yv.x) + rel_term(xv.y, yv.y)
         + rel_term(xv.z, yv.z) + rel_term(xv.w, yv.w);
}

__global__ void __launch_bounds__(NTHREADS, 1)
rdl_fused_kernel(const float* __restrict__ x,
                 const float* __restrict__ y,
                 int n4, float inv_n, float* __restrict__ out)
{
    const float4* __restrict__ x4 = (const float4*)x;
    const float4* __restrict__ y4 = (const float4*)y;

    const int tid    = blockIdx.x * NTHREADS + threadIdx.x;
    const int stride = NBLOCKS * NTHREADS;

    float acc = 0.0f;

    if (n4 == stride * 16) {
        // Fast path: exactly 16 float4 per thread, unrolled x4 so the
        // compiler front-batches 8 independent LDG.128 per iteration.
        int i = tid;
        #pragma unroll 4
        for (int j = 0; j < 16; j += 4) {
            float4 xa = x4[i];              float4 ya = y4[i];
            float4 xb = x4[i +     stride]; float4 yb = y4[i +     stride];
            float4 xc = x4[i + 2 * stride]; float4 yc = y4[i + 2 * stride];
            float4 xd = x4[i + 3 * stride]; float4 yd = y4[i + 3 * stride];
            acc += quad(xa, ya);
            acc += quad(xb, yb);
            acc += quad(xc, yc);
            acc += quad(xd, yd);
            i += 4 * stride;
        }
    } else {
        for (int i = tid; i < n4; i += stride) {
            acc += quad(x4[i], y4[i]);
        }
    }

    // ---- block reduce ----
    #pragma unroll
    for (int off = 16; off > 0; off >>= 1)
        acc += __shfl_down_sync(0xFFFFFFFFu, acc, off);

    __shared__ float s_warp[NTHREADS / 32];
    int lane = threadIdx.x & 31;
    int wid  = threadIdx.x >> 5;
    if (lane == 0) s_warp[wid] = acc;
    __syncthreads();

    __shared__ bool s_is_last;
    if (threadIdx.x == 0) {
        float v = 0.0f;
        #pragma unroll
        for (int w = 0; w < NTHREADS / 32; w++) v += s_warp[w];
        g_partials[blockIdx.x] = v;
        __threadfence();
        unsigned int prev = atomicAdd(&g_count, 1u);
        s_is_last = (prev == (unsigned)(gridDim.x - 1));
    }
    __syncthreads();

    // ---- last block: deterministic final reduce over g_partials ----
    if (s_is_last) {
        float v = 0.0f;
        for (int i = threadIdx.x; i < NBLOCKS; i += NTHREADS)
            v += g_partials[i];

        #pragma unroll
        for (int off = 16; off > 0; off >>= 1)
            v += __shfl_down_sync(0xFFFFFFFFu, v, off);

        if (lane == 0) s_warp[wid] = v;
        __syncthreads();

        if (threadIdx.x == 0) {
            float t = 0.0f;
            #pragma unroll
            for (int w = 0; w < NTHREADS / 32; w++) t += s_warp[w];
            out[0]  = t * inv_n;
            g_count = 0;   // reset for next graph replay
        }
    }
}

extern "C" void kernel_launch(void* const* d_in, const int* in_sizes, int n_in,
                              void* d_out, int out_size)
{
    const float* x = (const float*)d_in[0];
    const float* y = (const float*)d_in[1];
    float* out = (float*)d_out;

    int n  = in_sizes[0];   // 33554432
    int n4 = n >> 2;

    rdl_fused_kernel<<<NBLOCKS, NTHREADS>>>(x, y, n4, 1.0f / (float)n, out);
}

// round 6
// speedup vs baseline: 1.2177x; 1.2177x over previous
#include <cuda_runtime.h>

// ---------------------------------------------------------------------------
// RelativeDifferenceLoss: mean over N of (y==0 ? |x-y| : |x-y|/y)
// Single fused kernel: R1's simple grid-stride streaming loop (low regs, high
// occupancy) + last-block-done final reduce (kills the 5.2us finisher kernel).
// ---------------------------------------------------------------------------

#define NBLOCKS   2368          // 148 SMs * 16
#define NTHREADS  256

__device__ float        g_partials[NBLOCKS];
__device__ unsigned int g_count = 0;   // reset by last block each launch

__device__ __forceinline__ float rel_term(float x, float y) {
    float ad = fabsf(x - y);
    return (y == 0.0f) ? ad : __fdividef(ad, y);   // signed y, matching reference
}

__global__ void __launch_bounds__(NTHREADS, 6)    // cap regs ~42 -> >=6 CTA/SM
rdl_fused_kernel(const float* __restrict__ x,
                 const float* __restrict__ y,
                 int n4, float inv_n, float* __restrict__ out)
{
    const float4* __restrict__ x4 = (const float4*)x;
    const float4* __restrict__ y4 = (const float4*)y;

    float acc = 0.0f;
    const int stride = NBLOCKS * NTHREADS;
    for (int i = blockIdx.x * NTHREADS + threadIdx.x; i < n4; i += stride) {
        float4 xv = x4[i];
        float4 yv = y4[i];
        acc += rel_term(xv.x, yv.x);
        acc += rel_term(xv.y, yv.y);
        acc += rel_term(xv.z, yv.z);
        acc += rel_term(xv.w, yv.w);
    }

    // ---- block reduce ----
    #pragma unroll
    for (int off = 16; off > 0; off >>= 1)
        acc += __shfl_down_sync(0xFFFFFFFFu, acc, off);

    __shared__ float s_warp[NTHREADS / 32];
    int lane = threadIdx.x & 31;
    int wid  = threadIdx.x >> 5;
    if (lane == 0) s_warp[wid] = acc;
    __syncthreads();

    __shared__ bool s_is_last;
    if (threadIdx.x == 0) {
        float v = 0.0f;
        #pragma unroll
        for (int w = 0; w < NTHREADS / 32; w++) v += s_warp[w];
        g_partials[blockIdx.x] = v;
        __threadfence();
        unsigned int prev = atomicAdd(&g_count, 1u);
        s_is_last = (prev == (unsigned)(gridDim.x - 1));
    }
    __syncthreads();

    // ---- last block: deterministic final reduce over g_partials ----
    if (s_is_last) {
        float v = 0.0f;
        for (int i = threadIdx.x; i < NBLOCKS; i += NTHREADS)
            v += g_partials[i];

        #pragma unroll
        for (int off = 16; off > 0; off >>= 1)
            v += __shfl_down_sync(0xFFFFFFFFu, v, off);

        if (lane == 0) s_warp[wid] = v;
        __syncthreads();

        if (threadIdx.x == 0) {
            float t = 0.0f;
            #pragma unroll
            for (int w = 0; w < NTHREADS / 32; w++) t += s_warp[w];
            out[0]  = t * inv_n;
            g_count = 0;   // reset for next graph replay
        }
    }
}

extern "C" void kernel_launch(void* const* d_in, const int* in_sizes, int n_in,
                              void* d_out, int out_size)
{
    const float* x = (const float*)d_in[0];
    const float* y = (const float*)d_in[1];
    float* out = (float*)d_out;

    int n  = in_sizes[0];   // 33554432
    int n4 = n >> 2;

    rdl_fused_kernel<<<NBLOCKS, NTHREADS>>>(x, y, n4, 1.0f / (float)n, out);
}

// round 7
// speedup vs baseline: 1.2531x; 1.0290x over previous
#include <cuda_runtime.h>

// ---------------------------------------------------------------------------
// RelativeDifferenceLoss: mean over N of (y==0 ? |x-y| : |x-y|/y)
// Fused single kernel. Main loop is byte-identical to R1's best (plain
// grid-stride, __launch_bounds__(256,1) so ptxas unrolls/pipelines freely);
// tail is the last-block-done reduce that replaces the 5.2us finisher.
// ---------------------------------------------------------------------------

#define NBLOCKS   2368          // 148 SMs * 16
#define NTHREADS  256

__device__ float        g_partials[NBLOCKS];
__device__ unsigned int g_count = 0;   // reset by last block each launch

__device__ __forceinline__ float rel_term(float x, float y) {
    float ad = fabsf(x - y);
    return (y == 0.0f) ? ad : __fdividef(ad, y);   // signed y, matching reference
}

__global__ void __launch_bounds__(NTHREADS, 1)    // R1's config: let ptxas pipeline
rdl_fused_kernel(const float* __restrict__ x,
                 const float* __restrict__ y,
                 int n4, float inv_n, float* __restrict__ out)
{
    const float4* __restrict__ x4 = (const float4*)x;
    const float4* __restrict__ y4 = (const float4*)y;

    float acc = 0.0f;
    const int stride = NBLOCKS * NTHREADS;
    for (int i = blockIdx.x * NTHREADS + threadIdx.x; i < n4; i += stride) {
        float4 xv = x4[i];
        float4 yv = y4[i];
        acc += rel_term(xv.x, yv.x);
        acc += rel_term(xv.y, yv.y);
        acc += rel_term(xv.z, yv.z);
        acc += rel_term(xv.w, yv.w);
    }

    // ---- block reduce ----
    #pragma unroll
    for (int off = 16; off > 0; off >>= 1)
        acc += __shfl_down_sync(0xFFFFFFFFu, acc, off);

    __shared__ float s_warp[NTHREADS / 32];
    int lane = threadIdx.x & 31;
    int wid  = threadIdx.x >> 5;
    if (lane == 0) s_warp[wid] = acc;
    __syncthreads();

    __shared__ bool s_is_last;
    if (threadIdx.x == 0) {
        float v = 0.0f;
        #pragma unroll
        for (int w = 0; w < NTHREADS / 32; w++) v += s_warp[w];
        g_partials[blockIdx.x] = v;
        __threadfence();
        unsigned int prev = atomicAdd(&g_count, 1u);
        s_is_last = (prev == (unsigned)(gridDim.x - 1));
    }
    __syncthreads();

    // ---- last block: deterministic final reduce over g_partials ----
    if (s_is_last) {
        float v = 0.0f;
        for (int i = threadIdx.x; i < NBLOCKS; i += NTHREADS)
            v += g_partials[i];

        #pragma unroll
        for (int off = 16; off > 0; off >>= 1)
            v += __shfl_down_sync(0xFFFFFFFFu, v, off);

        if (lane == 0) s_warp[wid] = v;
        __syncthreads();

        if (threadIdx.x == 0) {
            float t = 0.0f;
            #pragma unroll
            for (int w = 0; w < NTHREADS / 32; w++) t += s_warp[w];
            out[0]  = t * inv_n;
            g_count = 0;   // reset for next graph replay
        }
    }
}

extern "C" void kernel_launch(void* const* d_in, const int* in_sizes, int n_in,
                              void* d_out, int out_size)
{
    const float* x = (const float*)d_in[0];
    const float* y = (const float*)d_in[1];
    float* out = (float*)d_out;

    int n  = in_sizes[0];   // 33554432
    int n4 = n >> 2;

    rdl_fused_kernel<<<NBLOCKS, NTHREADS>>>(x, y, n4, 1.0f / (float)n, out);
}

// round 9
// speedup vs baseline: 1.2583x; 1.0042x over previous
#include <cuda_runtime.h>

// ---------------------------------------------------------------------------
// RelativeDifferenceLoss: mean over N of (y==0 ? |x-y| : |x-y|/y)
// Fused single kernel. Hot loop: 16 float4/thread, 2 pairs (4 independent
// LDG.128.CS) in flight per iteration, dual accumulators. MLP=4 at ~60% occ.
// Tail: last-block-done reduce (no finisher kernel).
// ---------------------------------------------------------------------------

#define NBLOCKS   2048          // 2048*256 = 2^19 threads; n4=2^23 -> 16/thread
#define NTHREADS  256

__device__ float        g_partials[NBLOCKS];
__device__ unsigned int g_count = 0;   // reset by last block each launch

__device__ __forceinline__ float rel_term(float x, float y) {
    float ad = fabsf(x - y);
    return (y == 0.0f) ? ad : __fdividef(ad, y);   // signed y, matching reference
}

__device__ __forceinline__ float quad(float4 xv, float4 yv) {
    return rel_term(xv.x, yv.x) + rel_term(xv.y, yv.y)
         + rel_term(xv.z, yv.z) + rel_term(xv.w, yv.w);
}

__global__ void __launch_bounds__(NTHREADS, 1)
rdl_fused_kernel(const float* __restrict__ x,
                 const float* __restrict__ y,
                 int n4, float inv_n, float* __restrict__ out)
{
    const float4* __restrict__ x4 = (const float4*)x;
    const float4* __restrict__ y4 = (const float4*)y;

    const int tid    = blockIdx.x * NTHREADS + threadIdx.x;
    const int stride = NBLOCKS * NTHREADS;

    float acc0 = 0.0f, acc1 = 0.0f;

    if (n4 == stride * 16) {
        // 8 iterations x 2 float4-pairs: 4 independent streaming LDG.128
        // front-batched per iteration (MLP=4), 16 data regs live.
        int i = tid;
        for (int j = 0; j < 8; j++) {
            float4 xa = __ldcs(&x4[i]);
            float4 ya = __ldcs(&y4[i]);
            float4 xb = __ldcs(&x4[i + stride]);
            float4 yb = __ldcs(&y4[i + stride]);
            acc0 += quad(xa, ya);
            acc1 += quad(xb, yb);
            i += 2 * stride;
        }
    } else {
        for (int i = tid; i < n4; i += stride)
            acc0 += quad(__ldcs(&x4[i]), __ldcs(&y4[i]));
    }

    float acc = acc0 + acc1;

    // ---- block reduce ----
    #pragma unroll
    for (int off = 16; off > 0; off >>= 1)
        acc += __shfl_down_sync(0xFFFFFFFFu, acc, off);

    __shared__ float s_warp[NTHREADS / 32];
    int lane = threadIdx.x & 31;
    int wid  = threadIdx.x >> 5;
    if (lane == 0) s_warp[wid] = acc;
    __syncthreads();

    __shared__ bool s_is_last;
    if (threadIdx.x == 0) {
        float v = 0.0f;
        #pragma unroll
        for (int w = 0; w < NTHREADS / 32; w++) v += s_warp[w];
        g_partials[blockIdx.x] = v;
        __threadfence();
        unsigned int prev = atomicAdd(&g_count, 1u);
        s_is_last = (prev == (unsigned)(gridDim.x - 1));
    }
    __syncthreads();

    // ---- last block: deterministic final reduce over g_partials ----
    if (s_is_last) {
        float v = 0.0f;
        for (int i = threadIdx.x; i < NBLOCKS; i += NTHREADS)
            v += g_partials[i];

        #pragma unroll
        for (int off = 16; off > 0; off >>= 1)
            v += __shfl_down_sync(0xFFFFFFFFu, v, off);

        if (lane == 0) s_warp[wid] = v;
        __syncthreads();

        if (threadIdx.x == 0) {
            float t = 0.0f;
            #pragma unroll
            for (int w = 0; w < NTHREADS / 32; w++) t += s_warp[w];
            out[0]  = t * inv_n;
            g_count = 0;   // reset for next graph replay
        }
    }
}

extern "C" void kernel_launch(void* const* d_in, const int* in_sizes, int n_in,
                              void* d_out, int out_size)
{
    const float* x = (const float*)d_in[0];
    const float* y = (const float*)d_in[1];
    float* out = (float*)d_out;

    int n  = in_sizes[0];   // 33554432
    int n4 = n >> 2;

    rdl_fused_kernel<<<NBLOCKS, NTHREADS>>>(x, y, n4, 1.0f / (float)n, out);
}

// round 11
// speedup vs baseline: 1.3213x; 1.0500x over previous
#include <cuda_runtime.h>
#include <cstdint>

// ---------------------------------------------------------------------------
// RelativeDifferenceLoss: mean over N of (y==0 ? |x-y| : |x-y|/y)
// Bulk-async (cp.async.bulk) G2S pipeline: 4-stage smem ring per CTA,
// copy-engine fetch instead of register LDG. Last-block-done final reduce.
// ---------------------------------------------------------------------------

#define GRID          2048
#define NTHREADS      256
#define STAGES        4
#define CHUNK_FLOATS  1024                 // per array per stage (4096 B)
#define CHUNK_BYTES   (CHUNK_FLOATS * 4)   // 4096
#define STAGE_TX      (2 * CHUNK_BYTES)    // 8192 (x + y)

__device__ float        g_partials[GRID];
__device__ unsigned int g_count = 0;

// ---- PTX helpers (self-contained) ----
__device__ __forceinline__ uint32_t smem_u32(const void* p) {
    uint32_t a;
    asm("{ .reg .u64 t; cvta.to.shared.u64 t, %1; cvt.u32.u64 %0, t; }"
        : "=r"(a) : "l"(p));
    return a;
}
__device__ __forceinline__ void mbar_init(uint32_t bar, uint32_t cnt) {
    asm volatile("mbarrier.init.shared.b64 [%0], %1;" :: "r"(bar), "r"(cnt) : "memory");
}
__device__ __forceinline__ void mbar_expect_tx(uint32_t bar, uint32_t bytes) {
    asm volatile("mbarrier.arrive.expect_tx.shared.b64 _, [%0], %1;"
                 :: "r"(bar), "r"(bytes) : "memory");
}
__device__ __forceinline__ void mbar_wait_parity(uint32_t bar, uint32_t phase) {
    asm volatile(
        "{\n\t"
        ".reg .pred P;\n\t"
        "WL%=:\n\t"
        "mbarrier.try_wait.parity.acquire.cta.shared::cta.b64 P, [%0], %1, 0x989680;\n\t"
        "@P bra WD%=;\n\t"
        "bra WL%=;\n\t"
        "WD%=:\n\t"
        "}"
        :: "r"(bar), "r"(phase) : "memory");
}
__device__ __forceinline__ void fence_proxy_async_cta() {
    asm volatile("fence.proxy.async.shared::cta;" ::: "memory");
}
__device__ __forceinline__ void bulk_g2s(uint32_t dst, const void* src,
                                         uint32_t bytes, uint32_t bar) {
    asm volatile(
        "cp.async.bulk.shared::cluster.global.mbarrier::complete_tx::bytes "
        "[%0], [%1], %2, [%3];"
        :: "r"(dst), "l"(src), "r"(bytes), "r"(bar) : "memory");
}

__device__ __forceinline__ float rel_term(float x, float y) {
    float ad = fabsf(x - y);
    return (y == 0.0f) ? ad : __fdividef(ad, y);   // signed y, matching reference
}

__global__ void __launch_bounds__(NTHREADS)
rdl_bulk_kernel(const float* __restrict__ x,
                const float* __restrict__ y,
                int n, float inv_n, float* __restrict__ out)
{
    __shared__ alignas(16) float sx[STAGES][CHUNK_FLOATS];
    __shared__ alignas(16) float sy[STAGES][CHUNK_FLOATS];
    __shared__ alignas(8)  unsigned long long s_bar[STAGES];
    __shared__ float s_warp[NTHREADS / 32];
    __shared__ bool  s_is_last;

    const int tid = threadIdx.x;
    float acc = 0.0f;

    const int nchunks = n / CHUNK_FLOATS;
    const bool fast = (n % CHUNK_FLOATS == 0) && (nchunks % GRID == 0);

    if (fast) {
        const int chunks_per_cta = nchunks / GRID;               // 16 for N=2^25
        const long long base = (long long)blockIdx.x * chunks_per_cta;

        uint32_t bar0 = smem_u32(&s_bar[0]);

        if (tid == 0) {
            #pragma unroll
            for (int s = 0; s < STAGES; s++) mbar_init(bar0 + 8u * s, 1);
            fence_proxy_async_cta();
            // prologue: fill the ring
            int pre = chunks_per_cta < STAGES ? chunks_per_cta : STAGES;
            for (int s = 0; s < pre; s++) {
                uint32_t bar = bar0 + 8u * s;
                mbar_expect_tx(bar, STAGE_TX);
                const float* xs = x + (base + s) * CHUNK_FLOATS;
                const float* ys = y + (base + s) * CHUNK_FLOATS;
                bulk_g2s(smem_u32(&sx[s][0]), xs, CHUNK_BYTES, bar);
                bulk_g2s(smem_u32(&sy[s][0]), ys, CHUNK_BYTES, bar);
            }
        }
        __syncthreads();

        for (int c = 0; c < chunks_per_cta; c++) {
            const int st = c & (STAGES - 1);
            const uint32_t ph = (c >> 2) & 1;          // parity of this stage use
            mbar_wait_parity(bar0 + 8u * st, ph);

            // 1024 floats = 256 float4: one per thread per array
            float4 xv = ((const float4*)&sx[st][0])[tid];
            float4 yv = ((const float4*)&sy[st][0])[tid];
            acc += rel_term(xv.x, yv.x);
            acc += rel_term(xv.y, yv.y);
            acc += rel_term(xv.z, yv.z);
            acc += rel_term(xv.w, yv.w);

            __syncthreads();   // all reads of stage done before refill

            int nc = c + STAGES;
            if (nc < chunks_per_cta && tid == 0) {
                uint32_t bar = bar0 + 8u * st;
                mbar_expect_tx(bar, STAGE_TX);
                const float* xs = x + (base + nc) * CHUNK_FLOATS;
                const float* ys = y + (base + nc) * CHUNK_FLOATS;
                bulk_g2s(smem_u32(&sx[st][0]), xs, CHUNK_BYTES, bar);
                bulk_g2s(smem_u32(&sy[st][0]), ys, CHUNK_BYTES, bar);
            }
        }
    } else {
        // generic fallback: plain grid-stride LDG
        int n4 = n >> 2;
        const float4* x4 = (const float4*)x;
        const float4* y4 = (const float4*)y;
        for (int i = blockIdx.x * NTHREADS + tid; i < n4; i += GRID * NTHREADS) {
            float4 xv = x4[i], yv = y4[i];
            acc += rel_term(xv.x, yv.x) + rel_term(xv.y, yv.y)
                 + rel_term(xv.z, yv.z) + rel_term(xv.w, yv.w);
        }
        for (int i = (n4 << 2) + blockIdx.x * NTHREADS + tid; i < n; i += GRID * NTHREADS)
            acc += rel_term(x[i], y[i]);
    }

    // ---- block reduce ----
    #pragma unroll
    for (int off = 16; off > 0; off >>= 1)
        acc += __shfl_down_sync(0xFFFFFFFFu, acc, off);

    int lane = tid & 31;
    int wid  = tid >> 5;
    if (lane == 0) s_warp[wid] = acc;
    __syncthreads();

    if (tid == 0) {
        float v = 0.0f;
        #pragma unroll
        for (int w = 0; w < NTHREADS / 32; w++) v += s_warp[w];
        g_partials[blockIdx.x] = v;
        __threadfence();
        unsigned int prev = atomicAdd(&g_count, 1u);
        s_is_last = (prev == (unsigned)(gridDim.x - 1));
    }
    __syncthreads();

    // ---- last block: deterministic final reduce ----
    if (s_is_last) {
        float v = 0.0f;
        for (int i = tid; i < GRID; i += NTHREADS)
            v += g_partials[i];

        #pragma unroll
        for (int off = 16; off > 0; off >>= 1)
            v += __shfl_down_sync(0xFFFFFFFFu, v, off);

        if (lane == 0) s_warp[wid] = v;
        __syncthreads();

        if (tid == 0) {
            float t = 0.0f;
            #pragma unroll
            for (int w = 0; w < NTHREADS / 32; w++) t += s_warp[w];
            out[0]  = t * inv_n;
            g_count = 0;   // reset for next graph replay
        }
    }
}

extern "C" void kernel_launch(void* const* d_in, const int* in_sizes, int n_in,
                              void* d_out, int out_size)
{
    const float* x = (const float*)d_in[0];
    const float* y = (const float*)d_in[1];
    float* out = (float*)d_out;

    int n = in_sizes[0];   // 33554432

    rdl_bulk_kernel<<<GRID, NTHREADS>>>(x, y, n, 1.0f / (float)n, out);
}

// round 12
// speedup vs baseline: 1.4856x; 1.1244x over previous
#include <cuda_runtime.h>
#include <cstdint>

// ---------------------------------------------------------------------------
// RelativeDifferenceLoss: mean over N of (y==0 ? |x-y| : |x-y|/y)
// Persistent bulk-async pipeline: 296 CTAs (2/SM), 6-stage x 16KB dynamic
// smem ring per CTA, cp.async.bulk G2S, early refill, last-block final reduce.
// ---------------------------------------------------------------------------

#define GRID          296                  // 2 CTAs x 148 SMs, persistent
#define NTHREADS      256
#define STAGES        6
#define CHUNK_FLOATS  2048                 // per array per stage (8192 B)
#define CHUNK_BYTES   (CHUNK_FLOATS * 4)   // 8192
#define STAGE_FLOATS  (2 * CHUNK_FLOATS)   // x + y interleaved per stage
#define STAGE_TX      (2 * CHUNK_BYTES)    // 16384
#define SMEM_BYTES    (STAGES * STAGE_TX)  // 98304 (96 KB)

__device__ float        g_partials[GRID];
__device__ unsigned int g_count = 0;

// ---- PTX helpers ----
__device__ __forceinline__ uint32_t smem_u32(const void* p) {
    uint32_t a;
    asm("{ .reg .u64 t; cvta.to.shared.u64 t, %1; cvt.u32.u64 %0, t; }"
        : "=r"(a) : "l"(p));
    return a;
}
__device__ __forceinline__ void mbar_init(uint32_t bar, uint32_t cnt) {
    asm volatile("mbarrier.init.shared.b64 [%0], %1;" :: "r"(bar), "r"(cnt) : "memory");
}
__device__ __forceinline__ void mbar_expect_tx(uint32_t bar, uint32_t bytes) {
    asm volatile("mbarrier.arrive.expect_tx.shared.b64 _, [%0], %1;"
                 :: "r"(bar), "r"(bytes) : "memory");
}
__device__ __forceinline__ void mbar_wait_parity(uint32_t bar, uint32_t phase) {
    asm volatile(
        "{\n\t"
        ".reg .pred P;\n\t"
        "WL%=:\n\t"
        "mbarrier.try_wait.parity.acquire.cta.shared::cta.b64 P, [%0], %1, 0x989680;\n\t"
        "@P bra WD%=;\n\t"
        "bra WL%=;\n\t"
        "WD%=:\n\t"
        "}"
        :: "r"(bar), "r"(phase) : "memory");
}
__device__ __forceinline__ void fence_proxy_async_cta() {
    asm volatile("fence.proxy.async.shared::cta;" ::: "memory");
}
__device__ __forceinline__ void bulk_g2s(uint32_t dst, const void* src,
                                         uint32_t bytes, uint32_t bar) {
    asm volatile(
        "cp.async.bulk.shared::cluster.global.mbarrier::complete_tx::bytes "
        "[%0], [%1], %2, [%3];"
        :: "r"(dst), "l"(src), "r"(bytes), "r"(bar) : "memory");
}

__device__ __forceinline__ float rel_term(float x, float y) {
    float ad = fabsf(x - y);
    return (y == 0.0f) ? ad : __fdividef(ad, y);   // signed y, matching reference
}
__device__ __forceinline__ float quad(float4 xv, float4 yv) {
    return rel_term(xv.x, yv.x) + rel_term(xv.y, yv.y)
         + rel_term(xv.z, yv.z) + rel_term(xv.w, yv.w);
}

extern __shared__ float sm_ring[];   // [STAGES][2*CHUNK_FLOATS]: x then y

__global__ void __launch_bounds__(NTHREADS)
rdl_bulk_kernel(const float* __restrict__ x,
                const float* __restrict__ y,
                int n, float inv_n, float* __restrict__ out)
{
    __shared__ alignas(8) unsigned long long s_bar[STAGES];
    __shared__ float s_warp[NTHREADS / 32];
    __shared__ bool  s_is_last;

    const int tid = threadIdx.x;
    float acc = 0.0f;

    const int nchunks = n / CHUNK_FLOATS;
    const bool fast = (n % CHUNK_FLOATS == 0);

    if (fast) {
        // grid-stride over chunks: CTA b handles chunks b, b+GRID, b+2*GRID, ...
        const int iters = (nchunks - (int)blockIdx.x + GRID - 1) / GRID;
        const uint32_t bar0 = smem_u32(&s_bar[0]);

        if (tid == 0) {
            #pragma unroll
            for (int s = 0; s < STAGES; s++) mbar_init(bar0 + 8u * s, 1);
            fence_proxy_async_cta();
            int pre = iters < STAGES ? iters : STAGES;
            for (int s = 0; s < pre; s++) {
                uint32_t bar = bar0 + 8u * s;
                long long c = (long long)blockIdx.x + (long long)s * GRID;
                mbar_expect_tx(bar, STAGE_TX);
                bulk_g2s(smem_u32(&sm_ring[s * STAGE_FLOATS]),
                         x + c * CHUNK_FLOATS, CHUNK_BYTES, bar);
                bulk_g2s(smem_u32(&sm_ring[s * STAGE_FLOATS + CHUNK_FLOATS]),
                         y + c * CHUNK_FLOATS, CHUNK_BYTES, bar);
            }
        }
        __syncthreads();

        int st = 0, ph = 0;                 // consumer cursor
        for (int j = 0; j < iters; j++) {
            mbar_wait_parity(bar0 + 8u * st, (uint32_t)ph);

            // stage -> registers: 2 float4 per array per thread
            const float4* sxv = (const float4*)&sm_ring[st * STAGE_FLOATS];
            const float4* syv = (const float4*)&sm_ring[st * STAGE_FLOATS + CHUNK_FLOATS];
            float4 xa = sxv[tid];
            float4 xb = sxv[tid + NTHREADS];
            float4 ya = syv[tid];
            float4 yb = syv[tid + NTHREADS];

            __syncthreads();                 // stage fully consumed

            // early refill: get the TMA request in flight before computing
            if (tid == 0 && j + STAGES < iters) {
                uint32_t bar = bar0 + 8u * st;
                long long c = (long long)blockIdx.x + (long long)(j + STAGES) * GRID;
                mbar_expect_tx(bar, STAGE_TX);
                bulk_g2s(smem_u32(&sm_ring[st * STAGE_FLOATS]),
                         x + c * CHUNK_FLOATS, CHUNK_BYTES, bar);
                bulk_g2s(smem_u32(&sm_ring[st * STAGE_FLOATS + CHUNK_FLOATS]),
                         y + c * CHUNK_FLOATS, CHUNK_BYTES, bar);
            }

            acc += quad(xa, ya);
            acc += quad(xb, yb);

            if (++st == STAGES) { st = 0; ph ^= 1; }
        }
    } else {
        // generic fallback: plain grid-stride LDG
        int n4 = n >> 2;
        const float4* x4 = (const float4*)x;
        const float4* y4 = (const float4*)y;
        for (int i = blockIdx.x * NTHREADS + tid; i < n4; i += GRID * NTHREADS) {
            float4 xv = x4[i], yv = y4[i];
            acc += quad(xv, yv);
        }
        for (int i = (n4 << 2) + blockIdx.x * NTHREADS + tid; i < n; i += GRID * NTHREADS)
            acc += rel_term(x[i], y[i]);
    }

    // ---- block reduce ----
    #pragma unroll
    for (int off = 16; off > 0; off >>= 1)
        acc += __shfl_down_sync(0xFFFFFFFFu, acc, off);

    int lane = tid & 31;
    int wid  = tid >> 5;
    if (lane == 0) s_warp[wid] = acc;
    __syncthreads();

    if (tid == 0) {
        float v = 0.0f;
        #pragma unroll
        for (int w = 0; w < NTHREADS / 32; w++) v += s_warp[w];
        g_partials[blockIdx.x] = v;
        __threadfence();
        unsigned int prev = atomicAdd(&g_count, 1u);
        s_is_last = (prev == (unsigned)(gridDim.x - 1));
    }
    __syncthreads();

    // ---- last block: deterministic final reduce ----
    if (s_is_last) {
        float v = 0.0f;
        for (int i = tid; i < GRID; i += NTHREADS)
            v += g_partials[i];

        #pragma unroll
        for (int off = 16; off > 0; off >>= 1)
            v += __shfl_down_sync(0xFFFFFFFFu, v, off);

        if (lane == 0) s_warp[wid] = v;
        __syncthreads();

        if (tid == 0) {
            float t = 0.0f;
            #pragma unroll
            for (int w = 0; w < NTHREADS / 32; w++) t += s_warp[w];
            out[0]  = t * inv_n;
            g_count = 0;   // reset for next graph replay
        }
    }
}

extern "C" void kernel_launch(void* const* d_in, const int* in_sizes, int n_in,
                              void* d_out, int out_size)
{
    const float* x = (const float*)d_in[0];
    const float* y = (const float*)d_in[1];
    float* out = (float*)d_out;

    int n = in_sizes[0];   // 33554432

    // Opt into 96KB dynamic smem (state-setting call, idempotent, no alloc).
    cudaFuncSetAttribute(rdl_bulk_kernel,
                         cudaFuncAttributeMaxDynamicSharedMemorySize, SMEM_BYTES);

    rdl_bulk_kernel<<<GRID, NTHREADS, SMEM_BYTES>>>(x, y, n, 1.0f / (float)n, out);
}